// round 9
// baseline (speedup 1.0000x reference)
#include <cuda_runtime.h>
#include <cstdint>
#include <cstddef>

#define NB 4
#define NL 2048
#define NH 16
#define ND 64
#define BQ 128
#define BK 64
#define NT 128
#define NHD (NH*ND)

// paired fragment superblock: 32 lanes x 4 words (2 fragments) + 4 pad = 132 words
#define PBW 132

__device__ __forceinline__ float ex2f(float x){
    float r; asm("ex2.approx.ftz.f32 %0, %1;" : "=f"(r) : "f"(x)); return r;
}
__device__ __forceinline__ uint32_t totf(float x){
    uint32_t r; asm("cvt.rna.tf32.f32 %0, %1;" : "=r"(r) : "f"(x)); return r;
}
__device__ __forceinline__ void mma16888(float* d, const uint32_t* a, uint32_t b0, uint32_t b1){
    asm volatile("mma.sync.aligned.m16n8k8.row.col.f32.tf32.tf32.f32 "
        "{%0,%1,%2,%3}, {%4,%5,%6,%7}, {%8,%9}, {%0,%1,%2,%3};"
        : "+f"(d[0]), "+f"(d[1]), "+f"(d[2]), "+f"(d[3])
        : "r"(a[0]), "r"(a[1]), "r"(a[2]), "r"(a[3]), "r"(b0), "r"(b1));
}

__global__ __launch_bounds__(NT, 3)
void mha_tf32o(const float* __restrict__ Q, const float* __restrict__ K,
               const float* __restrict__ V, float* __restrict__ O)
{
    // single-buffered fragment tiles: 16896 B each, 33792 B total
    __shared__ uint32_t Ksm[32 * PBW];
    __shared__ uint32_t Vsm[32 * PBW];

    const int tid = threadIdx.x;
    const int wid = tid >> 5, lid = tid & 31;

    const int qt = (gridDim.x - 1) - blockIdx.x;   // heavy q-tiles launch first
    const int bh = blockIdx.y;
    const int b  = bh / NH, h = bh % NH;
    const int q0 = qt * BQ;
    const int mr0 = wid * 32;                      // warp's 32 rows in the Q tile
    const int jj = lid & 3;

    const float SC = 1.4426950408889634f / 8.0f;   // log2(e)/sqrt(64): base-2 softmax

    const float* Qh = Q + ((size_t)b * NL * NH + h) * ND;
    const float* Kh = K + ((size_t)b * NL * NH + h) * ND;
    const float* Vh = V + ((size_t)b * NL * NH + h) * ND;
    float*       Oh = O + ((size_t)b * NL * NH + h) * ND;

    // ---- Q rows -> tf32 A-fragments (2 m-tiles x 8 k-steps), pre-scaled ----
    uint32_t qA[2][8][4];
    {
        int rbase = q0 + mr0 + (lid >> 2);
        #pragma unroll
        for (int m = 0; m < 2; m++)
            #pragma unroll
            for (int ks = 0; ks < 8; ks++)
                #pragma unroll
                for (int i = 0; i < 4; i++){
                    int row = rbase + 16 * m + 8 * (i & 1);
                    int col = 8 * ks + jj + 4 * (i >> 1);
                    qA[m][ks][i] = totf(Qh[(size_t)row * NHD + col] * SC);
                }
    }

    float Oa[2][8][4];
    float ls[2][2];
    #pragma unroll
    for (int m = 0; m < 2; m++){
        ls[m][0] = 0.f; ls[m][1] = 0.f;
        #pragma unroll
        for (int n = 0; n < 8; n++)
            #pragma unroll
            for (int j = 0; j < 4; j++) Oa[m][n][j] = 0.f;
    }

    const int ntiles = 2 * qt + 2;
    const int rowtop = q0 + mr0 + 31;              // warp's largest q row

    #pragma unroll 1
    for (int t = 0; t < ntiles; t++){
        const int kbase = t * BK;
        const float* Kb = Kh + (size_t)kbase * NHD;
        const float* Vb = Vh + (size_t)kbase * NHD;

        // ---- load + convert K,V tile into paired fragment layout ----
        // K superblock (nt, kp): lane l words [0..3] = two B-fragments (ks=2kp,2kp+1)
        // V superblock (nt, np): kv-PERMUTED rows -> P C-frag relabels into A-frag
        #pragma unroll
        for (int it = 0; it < 4; it++){
            int idx = it * NT + tid;                 // 0..511
            int r = idx >> 3, ch = idx & 7;
            const float4* s4 = (const float4*)(Kb + (size_t)r * NHD + ch * 8);
            float4 f0 = s4[0], f1 = s4[1];
            int kpi = ch >> 1, hk = ch & 1;
            uint32_t* kd = Ksm + ((r >> 3) * 4 + kpi) * PBW + 16 * (r & 7) + 2 * hk;
            *(uint2*)(kd + 0)  = make_uint2(totf(f0.x), totf(f1.x));
            *(uint2*)(kd + 4)  = make_uint2(totf(f0.y), totf(f1.y));
            *(uint2*)(kd + 8)  = make_uint2(totf(f0.z), totf(f1.z));
            *(uint2*)(kd + 12) = make_uint2(totf(f0.w), totf(f1.w));

            int c = idx & 63, rb = idx >> 6;
            const float* vc = Vb + (size_t)(rb * 8) * NHD + c;
            float v0 = vc[0*NHD], v1 = vc[1*NHD], v2 = vc[2*NHD], v3 = vc[3*NHD];
            float v4 = vc[4*NHD], v5 = vc[5*NHD], v6 = vc[6*NHD], v7 = vc[7*NHD];
            int npi = c >> 4, hv = (c >> 3) & 1, colin = c & 7;
            uint32_t* vd = Vsm + (rb * 4 + npi) * PBW + 16 * colin + 2 * hv;
            *(uint2*)(vd + 0)  = make_uint2(totf(v0), totf(v1));
            *(uint2*)(vd + 4)  = make_uint2(totf(v2), totf(v3));
            *(uint2*)(vd + 8)  = make_uint2(totf(v4), totf(v5));
            *(uint2*)(vd + 12) = make_uint2(totf(v6), totf(v7));
        }
        __syncthreads();

        const bool diag = (kbase >= q0);

        #pragma unroll
        for (int nt = 0; nt < 8; nt++){
            if (diag && (kbase + 8 * nt > rowtop)) continue;   // warp-uniform skip

            // QK^T for this 8-col kv block
            float S4[2][4];
            #pragma unroll
            for (int m = 0; m < 2; m++)
                #pragma unroll
                for (int j = 0; j < 4; j++) S4[m][j] = 0.f;
            #pragma unroll
            for (int kpp = 0; kpp < 4; kpp++){
                uint4 kb = *(const uint4*)(Ksm + (nt * 4 + kpp) * PBW + 4 * lid);
                mma16888(S4[0], qA[0][2*kpp],   kb.x, kb.y);
                mma16888(S4[1], qA[1][2*kpp],   kb.x, kb.y);
                mma16888(S4[0], qA[0][2*kpp+1], kb.z, kb.w);
                mma16888(S4[1], qA[1][2*kpp+1], kb.z, kb.w);
            }

            // softmax + mask + direct C->A relabel (V rows kv-permuted in smem)
            uint32_t pA[2][4];
            #pragma unroll
            for (int m = 0; m < 2; m++){
                float p0 = ex2f(S4[m][0]);
                float p1 = ex2f(S4[m][1]);
                float p2 = ex2f(S4[m][2]);
                float p3 = ex2f(S4[m][3]);
                if (diag){
                    int rg = q0 + mr0 + 16 * m + (lid >> 2);
                    int cg = kbase + 8 * nt + 2 * jj;
                    if (cg     > rg)     p0 = 0.f;
                    if (cg + 1 > rg)     p1 = 0.f;
                    if (cg     > rg + 8) p2 = 0.f;
                    if (cg + 1 > rg + 8) p3 = 0.f;
                }
                ls[m][0] += p0 + p1;
                ls[m][1] += p2 + p3;
                pA[m][0] = totf(p0);   // (r,   k=j)   = logical kv 2j
                pA[m][1] = totf(p2);   // (r+8, k=j)
                pA[m][2] = totf(p1);   // (r,   k=j+4) = logical kv 2j+1
                pA[m][3] = totf(p3);   // (r+8, k=j+4)
            }

            // PV accumulate (k-step = nt), paired V fragments
            #pragma unroll
            for (int npp = 0; npp < 4; npp++){
                uint4 vb = *(const uint4*)(Vsm + (nt * 4 + npp) * PBW + 4 * lid);
                mma16888(Oa[0][2*npp],   pA[0], vb.x, vb.y);
                mma16888(Oa[1][2*npp],   pA[1], vb.x, vb.y);
                mma16888(Oa[0][2*npp+1], pA[0], vb.z, vb.w);
                mma16888(Oa[1][2*npp+1], pA[1], vb.z, vb.w);
            }
        }
        __syncthreads();
    }

    // ---- epilogue: quad-reduce row sums, normalize, store ----
    #pragma unroll
    for (int m = 0; m < 2; m++){
        float s0 = ls[m][0], s1 = ls[m][1];
        s0 += __shfl_xor_sync(0xffffffffu, s0, 1);
        s0 += __shfl_xor_sync(0xffffffffu, s0, 2);
        s1 += __shfl_xor_sync(0xffffffffu, s1, 1);
        s1 += __shfl_xor_sync(0xffffffffu, s1, 2);
        float i0 = 1.f / s0, i1 = 1.f / s1;
        int rg = q0 + mr0 + 16 * m + (lid >> 2);
        float* o0 = Oh + (size_t)rg * NHD + 2 * jj;
        float* o1 = o0 + 8 * (size_t)NHD;
        #pragma unroll
        for (int n = 0; n < 8; n++){
            *(float2*)(o0 + 8 * n) = make_float2(Oa[m][n][0] * i0, Oa[m][n][1] * i0);
            *(float2*)(o1 + 8 * n) = make_float2(Oa[m][n][2] * i1, Oa[m][n][3] * i1);
        }
    }
}

extern "C" void kernel_launch(void* const* d_in, const int* in_sizes, int n_in,
                              void* d_out, int out_size)
{
    const float* q = (const float*)d_in[0];
    const float* k = (const float*)d_in[1];
    const float* v = (const float*)d_in[2];
    float* o = (float*)d_out;
    dim3 grid(NL / BQ, NB * NH);   // (16, 64)
    mha_tf32o<<<grid, NT>>>(q, k, v, o);
}

// round 10
// speedup vs baseline: 2.2479x; 2.2479x over previous
#include <cuda_runtime.h>
#include <cuda_fp16.h>
#include <cstdint>
#include <cstddef>

#define NB 4
#define NL 2048
#define NH 16
#define ND 64
#define BQ 128
#define BK 64
#define NT 128
#define NHD (NH*ND)

// superblock = 32 lanes x 16B = 128 words; 16 superblocks per K (or V) tile = 8KB
#define SBW 128

__device__ __forceinline__ float ex2f(float x){
    float r; asm("ex2.approx.ftz.f32 %0, %1;" : "=f"(r) : "f"(x)); return r;
}
__device__ __forceinline__ uint32_t h2(float a, float b){
    __half2 h = __floats2half2_rn(a, b);
    return *reinterpret_cast<uint32_t*>(&h);
}
__device__ __forceinline__ void mma16816(float* d, const uint32_t* a, uint32_t b0, uint32_t b1){
    asm volatile("mma.sync.aligned.m16n8k16.row.col.f32.f16.f16.f32 "
        "{%0,%1,%2,%3}, {%4,%5,%6,%7}, {%8,%9}, {%0,%1,%2,%3};"
        : "+f"(d[0]), "+f"(d[1]), "+f"(d[2]), "+f"(d[3])
        : "r"(a[0]), "r"(a[1]), "r"(a[2]), "r"(a[3]), "r"(b0), "r"(b1));
}

// ---- phase A: prefetch K,V tile gmem -> registers ----
// slot s = it*128+tid -> superblock sb = 4*it+wid, lane = lid (each thread: 4 slots)
// K sb (nt,kq): lane needs K[8nt+g][32kq+2t + {0,8,16,24}] pairs  (g=lid>>2, t=lid&3)
// V sb (kp,npq): lane needs V[16kp+2t + {0,1,8,9}][16npq+g, +8]
__device__ __forceinline__ void tile_load(const float* Kb, const float* Vb,
                                          int wid, int lid,
                                          float2 kr[4][4], float vr[4][8]){
    const int g = lid >> 2, t = lid & 3;
    #pragma unroll
    for (int it = 0; it < 4; it++){
        int sb = 4 * it + wid;
        int nt = sb >> 1, kq = sb & 1;
        const float* kbase = Kb + (size_t)(8 * nt + g) * NHD + 32 * kq + 2 * t;
        #pragma unroll
        for (int j = 0; j < 4; j++) kr[it][j] = *(const float2*)(kbase + 8 * j);
        int kp = sb >> 2, npq = sb & 3;
        const float* vbase = Vb + (size_t)(16 * kp + 2 * t) * NHD + 16 * npq + g;
        vr[it][0] = vbase[0];
        vr[it][1] = vbase[(size_t)1 * NHD];
        vr[it][2] = vbase[(size_t)8 * NHD];
        vr[it][3] = vbase[(size_t)9 * NHD];
        vr[it][4] = vbase[8];
        vr[it][5] = vbase[(size_t)1 * NHD + 8];
        vr[it][6] = vbase[(size_t)8 * NHD + 8];
        vr[it][7] = vbase[(size_t)9 * NHD + 8];
    }
}
// ---- phase C: convert + store registers -> fragment smem (1 STS.128 per slot) ----
__device__ __forceinline__ void tile_store(uint32_t* Ksm, uint32_t* Vsm,
                                           int wid, int lid,
                                           const float2 kr[4][4], const float vr[4][8]){
    #pragma unroll
    for (int it = 0; it < 4; it++){
        int sb = 4 * it + wid;
        uint32_t* kd = Ksm + sb * SBW + 4 * lid;
        *(uint4*)kd = make_uint4(h2(kr[it][0].x, kr[it][0].y),
                                 h2(kr[it][1].x, kr[it][1].y),
                                 h2(kr[it][2].x, kr[it][2].y),
                                 h2(kr[it][3].x, kr[it][3].y));
        uint32_t* vd = Vsm + sb * SBW + 4 * lid;
        *(uint4*)vd = make_uint4(h2(vr[it][0], vr[it][1]),   // b0: kv rows 2t,2t+1
                                 h2(vr[it][2], vr[it][3]),   // b1: kv rows 2t+8,2t+9
                                 h2(vr[it][4], vr[it][5]),   // b0, hd col +8
                                 h2(vr[it][6], vr[it][7]));  // b1, hd col +8
    }
}

__global__ __launch_bounds__(NT, 2)
void mha_fp16(const float* __restrict__ Q, const float* __restrict__ K,
              const float* __restrict__ V, float* __restrict__ O)
{
    __shared__ uint32_t Ksm[2][16 * SBW];
    __shared__ uint32_t Vsm[2][16 * SBW];

    const int tid = threadIdx.x;
    const int wid = tid >> 5, lid = tid & 31;
    const int g = lid >> 2, t = lid & 3;

    const int qt = (gridDim.x - 1) - blockIdx.x;   // heavy q-tiles launch first
    const int bh = blockIdx.y;
    const int b  = bh / NH, h = bh % NH;
    const int q0 = qt * BQ;
    const int mr0 = wid * 32;                      // warp's 32 rows in the Q tile

    const float SC = 1.4426950408889634f / 8.0f;   // log2(e)/sqrt(64): base-2 softmax

    const float* Qh = Q + ((size_t)b * NL * NH + h) * ND;
    const float* Kh = K + ((size_t)b * NL * NH + h) * ND;
    const float* Vh = V + ((size_t)b * NL * NH + h) * ND;
    float*       Oh = O + ((size_t)b * NL * NH + h) * ND;

    // ---- Q rows -> fp16 A-fragments (2 m-tiles x 4 k16-steps), pre-scaled ----
    uint32_t qA[2][4][4];
    {
        #pragma unroll
        for (int m = 0; m < 2; m++)
            #pragma unroll
            for (int ks = 0; ks < 4; ks++){
                const float* r0 = Qh + (size_t)(q0 + mr0 + 16 * m + g) * NHD + 16 * ks + 2 * t;
                const float* r1 = r0 + (size_t)8 * NHD;
                float2 f0 = *(const float2*)(r0);
                float2 f1 = *(const float2*)(r1);
                float2 f2 = *(const float2*)(r0 + 8);
                float2 f3 = *(const float2*)(r1 + 8);
                qA[m][ks][0] = h2(f0.x * SC, f0.y * SC);
                qA[m][ks][1] = h2(f1.x * SC, f1.y * SC);
                qA[m][ks][2] = h2(f2.x * SC, f2.y * SC);
                qA[m][ks][3] = h2(f3.x * SC, f3.y * SC);
            }
    }

    float Oa[2][8][4];
    float ls[2][2];
    #pragma unroll
    for (int m = 0; m < 2; m++){
        ls[m][0] = 0.f; ls[m][1] = 0.f;
        #pragma unroll
        for (int n = 0; n < 8; n++)
            #pragma unroll
            for (int j = 0; j < 4; j++) Oa[m][n][j] = 0.f;
    }

    const int ntiles = 2 * qt + 2;
    const int rowtop = q0 + mr0 + 31;              // warp's largest q row

    // ---- prologue: tile 0 -> buffer 0 ----
    {
        float2 kr[4][4]; float vr[4][8];
        tile_load(Kh, Vh, wid, lid, kr, vr);
        tile_store(Ksm[0], Vsm[0], wid, lid, kr, vr);
    }
    __syncthreads();

    #pragma unroll 1
    for (int tt = 0; tt < ntiles; tt++){
        const int kbase = tt * BK;
        const bool havenext = (tt + 1 < ntiles);

        // phase A: issue next tile's global loads
        float2 kr[4][4]; float vr[4][8];
        if (havenext)
            tile_load(Kh + (size_t)(kbase + BK) * NHD, Vh + (size_t)(kbase + BK) * NHD,
                      wid, lid, kr, vr);

        // phase B: compute on current buffers
        const uint32_t* Ks = Ksm[tt & 1];
        const uint32_t* Vs = Vsm[tt & 1];
        const bool diag = (kbase >= q0);

        #pragma unroll
        for (int kp = 0; kp < 4; kp++){                       // 16 kv cols per step
            if (diag && (kbase + 16 * kp > rowtop)) continue; // warp-uniform skip

            // ---- QK^T for kv cols [16kp, 16kp+16) ----
            float S4[2][2][4];                                 // [h][m][4]
            #pragma unroll
            for (int hh = 0; hh < 2; hh++)
                #pragma unroll
                for (int m = 0; m < 2; m++)
                    #pragma unroll
                    for (int j = 0; j < 4; j++) S4[hh][m][j] = 0.f;
            #pragma unroll
            for (int hh = 0; hh < 2; hh++){
                int nt = 2 * kp + hh;
                #pragma unroll
                for (int kq = 0; kq < 2; kq++){
                    uint4 kb = *(const uint4*)(Ks + (nt * 2 + kq) * SBW + 4 * lid);
                    mma16816(S4[hh][0], qA[0][2*kq],   kb.x, kb.y);
                    mma16816(S4[hh][0], qA[0][2*kq+1], kb.z, kb.w);
                    mma16816(S4[hh][1], qA[1][2*kq],   kb.x, kb.y);
                    mma16816(S4[hh][1], qA[1][2*kq+1], kb.z, kb.w);
                }
            }

            // ---- softmax + mask + in-lane pack to fp16 A-fragments ----
            uint32_t pA[2][4];
            #pragma unroll
            for (int m = 0; m < 2; m++){
                #pragma unroll
                for (int hh = 0; hh < 2; hh++){
                    float p0 = ex2f(S4[hh][m][0]);
                    float p1 = ex2f(S4[hh][m][1]);
                    float p2 = ex2f(S4[hh][m][2]);
                    float p3 = ex2f(S4[hh][m][3]);
                    if (diag){
                        int rg = q0 + mr0 + 16 * m + g;
                        int cg = kbase + 8 * (2 * kp + hh) + 2 * t;
                        if (cg     > rg)     p0 = 0.f;
                        if (cg + 1 > rg)     p1 = 0.f;
                        if (cg     > rg + 8) p2 = 0.f;
                        if (cg + 1 > rg + 8) p3 = 0.f;
                    }
                    ls[m][0] += p0 + p1;
                    ls[m][1] += p2 + p3;
                    pA[m][2*hh]     = h2(p0, p1);   // rows g,    kv cols 16kp+8hh+2t..
                    pA[m][2*hh + 1] = h2(p2, p3);   // rows g+8
                }
            }

            // ---- PV accumulate (k16-step = kp) ----
            #pragma unroll
            for (int npq = 0; npq < 4; npq++){
                uint4 vb = *(const uint4*)(Vs + (kp * 4 + npq) * SBW + 4 * lid);
                mma16816(Oa[0][2*npq],   pA[0], vb.x, vb.y);
                mma16816(Oa[0][2*npq+1], pA[0], vb.z, vb.w);
                mma16816(Oa[1][2*npq],   pA[1], vb.x, vb.y);
                mma16816(Oa[1][2*npq+1], pA[1], vb.z, vb.w);
            }
        }

        // phase C: convert + store next tile into the other buffer
        if (havenext)
            tile_store(Ksm[(tt + 1) & 1], Vsm[(tt + 1) & 1], wid, lid, kr, vr);
        __syncthreads();
    }

    // ---- epilogue: quad-reduce row sums, normalize, store ----
    #pragma unroll
    for (int m = 0; m < 2; m++){
        float s0 = ls[m][0], s1 = ls[m][1];
        s0 += __shfl_xor_sync(0xffffffffu, s0, 1);
        s0 += __shfl_xor_sync(0xffffffffu, s0, 2);
        s1 += __shfl_xor_sync(0xffffffffu, s1, 1);
        s1 += __shfl_xor_sync(0xffffffffu, s1, 2);
        float i0 = 1.f / s0, i1 = 1.f / s1;
        int rg = q0 + mr0 + 16 * m + g;
        float* o0 = Oh + (size_t)rg * NHD + 2 * t;
        float* o1 = o0 + 8 * (size_t)NHD;
        #pragma unroll
        for (int n = 0; n < 8; n++){
            *(float2*)(o0 + 8 * n) = make_float2(Oa[m][n][0] * i0, Oa[m][n][1] * i0);
            *(float2*)(o1 + 8 * n) = make_float2(Oa[m][n][2] * i1, Oa[m][n][3] * i1);
        }
    }
}

extern "C" void kernel_launch(void* const* d_in, const int* in_sizes, int n_in,
                              void* d_out, int out_size)
{
    const float* q = (const float*)d_in[0];
    const float* k = (const float*)d_in[1];
    const float* v = (const float*)d_in[2];
    float* o = (float*)d_out;
    dim3 grid(NL / BQ, NB * NH);   // (16, 64)
    mha_fp16<<<grid, NT>>>(q, k, v, o);
}